// round 1
// baseline (speedup 1.0000x reference)
#include <cuda_runtime.h>
#include <cuda_bf16.h>

// Problem constants (match reference)
#define BATCH_SIZE_D 8388608.0
#define REG1 0.01
#define REG2 0.001
#define LOG_CLAMP -100.0f

// Cross-block accumulators: [0]=bce_sum, [1]=count, [2]=w1_sumsq, [3]=w2_sumsq
__device__ double g_acc[4];

__global__ void zero_acc_kernel() {
    if (threadIdx.x < 4) g_acc[threadIdx.x] = 0.0;
}

__device__ __forceinline__ float warp_reduce(float v) {
    #pragma unroll
    for (int off = 16; off > 0; off >>= 1)
        v += __shfl_xor_sync(0xFFFFFFFFu, v, off);
    return v;
}

__global__ void __launch_bounds__(256) fused_reduce_kernel(
    const float4* __restrict__ p4,
    const float4* __restrict__ l4,
    const float4* __restrict__ w14,
    const float4* __restrict__ w24,
    int nb4, int n14, int n24)
{
    float bce = 0.0f, cnt = 0.0f, s1 = 0.0f, s2 = 0.0f;

    const int tid    = blockIdx.x * blockDim.x + threadIdx.x;
    const int stride = gridDim.x * blockDim.x;

    // --- BCE + accuracy over model_outputs / labels ---
    for (int i = tid; i < nb4; i += stride) {
        float4 pv = p4[i];
        float4 lv = l4[i];
        float pp[4] = {pv.x, pv.y, pv.z, pv.w};
        float ll[4] = {lv.x, lv.y, lv.z, lv.w};
        #pragma unroll
        for (int c = 0; c < 4; c++) {
            float lp  = fmaxf(logf(pp[c]),    LOG_CLAMP);   // log(p), clamped (handles p=0 -> -inf)
            float lq  = fmaxf(log1pf(-pp[c]), LOG_CLAMP);   // log(1-p), clamped
            bce = fmaf(ll[c], lp, bce);
            bce = fmaf(1.0f - ll[c], lq, bce);
            cnt += (fabsf(pp[c] - ll[c]) < 0.5f) ? 1.0f : 0.0f;
        }
    }

    // --- ||w1||^2 ---
    for (int i = tid; i < n14; i += stride) {
        float4 v = w14[i];
        s1 = fmaf(v.x, v.x, s1);
        s1 = fmaf(v.y, v.y, s1);
        s1 = fmaf(v.z, v.z, s1);
        s1 = fmaf(v.w, v.w, s1);
    }

    // --- ||w2||^2 ---
    for (int i = tid; i < n24; i += stride) {
        float4 v = w24[i];
        s2 = fmaf(v.x, v.x, s2);
        s2 = fmaf(v.y, v.y, s2);
        s2 = fmaf(v.z, v.z, s2);
        s2 = fmaf(v.w, v.w, s2);
    }

    // --- block reduction: warp shuffle -> shared -> warp 0 ---
    __shared__ float smem[8][4];   // 256 threads = 8 warps
    const int lane = threadIdx.x & 31;
    const int warp = threadIdx.x >> 5;

    bce = warp_reduce(bce);
    cnt = warp_reduce(cnt);
    s1  = warp_reduce(s1);
    s2  = warp_reduce(s2);

    if (lane == 0) {
        smem[warp][0] = bce;
        smem[warp][1] = cnt;
        smem[warp][2] = s1;
        smem[warp][3] = s2;
    }
    __syncthreads();

    if (warp == 0) {
        float v0 = (lane < 8) ? smem[lane][0] : 0.0f;
        float v1 = (lane < 8) ? smem[lane][1] : 0.0f;
        float v2 = (lane < 8) ? smem[lane][2] : 0.0f;
        float v3 = (lane < 8) ? smem[lane][3] : 0.0f;
        v0 = warp_reduce(v0);
        v1 = warp_reduce(v1);
        v2 = warp_reduce(v2);
        v3 = warp_reduce(v3);
        if (lane == 0) {
            atomicAdd(&g_acc[0], (double)v0);
            atomicAdd(&g_acc[1], (double)v1);
            atomicAdd(&g_acc[2], (double)v2);
            atomicAdd(&g_acc[3], (double)v3);
        }
    }
}

__global__ void finalize_kernel(float* __restrict__ out) {
    if (threadIdx.x == 0 && blockIdx.x == 0) {
        double bce = g_acc[0];
        double cnt = g_acc[1];
        double s1  = g_acc[2];
        double s2  = g_acc[3];
        double B = BATCH_SIZE_D;
        double cross = -bce / B;
        double reg = (REG1 * s1 + REG2 * s2) / (2.0 * B);
        out[0] = (float)(cross + reg);
        out[1] = (float)cnt;
    }
}

extern "C" void kernel_launch(void* const* d_in, const int* in_sizes, int n_in,
                              void* d_out, int out_size) {
    const float4* p4  = (const float4*)d_in[0];   // model_outputs
    const float4* l4  = (const float4*)d_in[1];   // labels
    const float4* w14 = (const float4*)d_in[2];   // w1
    const float4* w24 = (const float4*)d_in[3];   // w2
    float* out = (float*)d_out;

    const int nb4 = in_sizes[0] / 4;   // 2097152
    const int n14 = in_sizes[2] / 4;   // 4194304
    const int n24 = in_sizes[3] / 4;   // 1048576

    zero_acc_kernel<<<1, 32>>>();
    // 148 SMs * 8 blocks/SM, 256 threads each
    fused_reduce_kernel<<<1184, 256>>>(p4, l4, w14, w24, nb4, n14, n24);
    finalize_kernel<<<1, 32>>>(out);
}